// round 1
// baseline (speedup 1.0000x reference)
#include <cuda_runtime.h>
#include <cuda_bf16.h>
#include <math.h>

// Problem constants
#define B_SZ   2
#define N_SEQ  2048
#define D_MODEL 1024
#define N_HEADS 16
#define D_HEAD  64
#define M_ROWS (B_SZ * N_SEQ)          // 4096
#define QKV_COLS (3 * D_MODEL)         // 3072

// Scratch (static device globals: allowed; no cudaMalloc)
__device__ float g_qkv[M_ROWS * QKV_COLS];   // [B*N, 3D]  ~50 MB
__device__ float g_ctx[M_ROWS * D_MODEL];    // [B*N, D]   ~17 MB

// ---------------------------------------------------------------------------
// Simple tiled fp32 GEMM: C[M,N] = A[M,K] @ B[K,N], all row-major.
// BM=BN=64, BK=16, 256 threads, 4x4 per thread. Dims assumed divisible.
// ---------------------------------------------------------------------------
#define BM 64
#define BN 64
#define BK 16

__global__ __launch_bounds__(256) void gemm_f32(const float* __restrict__ A,
                                                const float* __restrict__ Bm,
                                                float* __restrict__ C,
                                                int M, int N, int K)
{
    __shared__ float As[BK][BM];
    __shared__ float Bs[BK][BN];

    const int tx = threadIdx.x & 15;   // 0..15
    const int ty = threadIdx.x >> 4;   // 0..15
    const int row0 = blockIdx.y * BM;
    const int col0 = blockIdx.x * BN;

    float acc[4][4] = {};

    for (int k0 = 0; k0 < K; k0 += BK) {
        // Load A tile (BM x BK) transposed into As[kk][mm]
        #pragma unroll
        for (int i = threadIdx.x; i < BM * BK; i += 256) {
            int mm = i >> 4;          // /BK
            int kk = i & 15;          // %BK
            As[kk][mm] = A[(size_t)(row0 + mm) * K + k0 + kk];
        }
        // Load B tile (BK x BN)
        #pragma unroll
        for (int i = threadIdx.x; i < BK * BN; i += 256) {
            int kk = i >> 6;          // /BN
            int nn = i & 63;          // %BN
            Bs[kk][nn] = Bm[(size_t)(k0 + kk) * N + col0 + nn];
        }
        __syncthreads();

        #pragma unroll
        for (int kk = 0; kk < BK; kk++) {
            float a[4], b[4];
            #pragma unroll
            for (int i = 0; i < 4; i++) a[i] = As[kk][ty * 4 + i];
            #pragma unroll
            for (int j = 0; j < 4; j++) b[j] = Bs[kk][tx * 4 + j];
            #pragma unroll
            for (int i = 0; i < 4; i++)
                #pragma unroll
                for (int j = 0; j < 4; j++)
                    acc[i][j] = fmaf(a[i], b[j], acc[i][j]);
        }
        __syncthreads();
    }

    #pragma unroll
    for (int i = 0; i < 4; i++)
        #pragma unroll
        for (int j = 0; j < 4; j++)
            C[(size_t)(row0 + ty * 4 + i) * N + col0 + tx * 4 + j] = acc[i][j];
}

// ---------------------------------------------------------------------------
// Causal attention, one block per (query row n, head h, batch b).
// Keeps the full probability row (N_SEQ floats) in shared memory, so the
// [B,H,N,N] attention tensor is only written to global if the harness output
// actually contains it.
// ---------------------------------------------------------------------------
__global__ __launch_bounds__(256) void attn_kernel(const float* __restrict__ qkv,
                                                   float* __restrict__ attn_out,
                                                   float* __restrict__ ctx,
                                                   int write_attn)
{
    const int n = blockIdx.x;   // query position
    const int h = blockIdx.y;   // head
    const int b = blockIdx.z;   // batch
    const int tid = threadIdx.x;

    __shared__ float q_s[D_HEAD];
    __shared__ float p[N_SEQ];       // scores -> probs
    __shared__ float red[256];

    const float* qrow = qkv + ((size_t)(b * N_SEQ + n) * QKV_COLS + h * D_HEAD);
    if (tid < D_HEAD) q_s[tid] = qrow[tid];
    __syncthreads();

    // scores for m <= n
    float local_max = -INFINITY;
    for (int m = tid; m <= n; m += 256) {
        const float* krow = qkv + ((size_t)(b * N_SEQ + m) * QKV_COLS + D_MODEL + h * D_HEAD);
        float s = 0.f;
        #pragma unroll
        for (int d = 0; d < D_HEAD; d++) s = fmaf(q_s[d], krow[d], s);
        s *= 0.125f;                 // 1/sqrt(64)
        p[m] = s;
        local_max = fmaxf(local_max, s);
    }

    // block-reduce max
    red[tid] = local_max;
    __syncthreads();
    #pragma unroll
    for (int s = 128; s > 0; s >>= 1) {
        if (tid < s) red[tid] = fmaxf(red[tid], red[tid + s]);
        __syncthreads();
    }
    const float mx = red[0];
    __syncthreads();

    // exp + sum
    float local_sum = 0.f;
    for (int m = tid; m <= n; m += 256) {
        float e = __expf(p[m] - mx);
        p[m] = e;
        local_sum += e;
    }
    red[tid] = local_sum;
    __syncthreads();
    #pragma unroll
    for (int s = 128; s > 0; s >>= 1) {
        if (tid < s) red[tid] += red[tid + s];
        __syncthreads();
    }
    const float inv = 1.f / red[0];
    __syncthreads();

    // normalize (and optionally emit attention row)
    if (write_attn) {
        float* arow = attn_out + ((size_t)((b * N_HEADS + h) * N_SEQ + n)) * N_SEQ;
        for (int m = tid; m <= n; m += 256) {
            float pv = p[m] * inv;
            p[m] = pv;
            arow[m] = pv;
        }
        for (int m = n + 1 + tid; m < N_SEQ; m += 256) arow[m] = 0.f;
    } else {
        for (int m = tid; m <= n; m += 256) p[m] *= inv;
    }
    __syncthreads();

    // ctx[d] = sum_m p[m] * v[m][d] ; 4 partial groups of 64 threads
    const int d = tid & (D_HEAD - 1);
    const int g = tid >> 6;          // 0..3
    float acc = 0.f;
    for (int m = g; m <= n; m += 4) {
        const float* vrow = qkv + ((size_t)(b * N_SEQ + m) * QKV_COLS + 2 * D_MODEL + h * D_HEAD);
        acc = fmaf(p[m], vrow[d], acc);
    }
    red[tid] = acc;
    __syncthreads();
    if (g == 0) {
        float o = red[d] + red[64 + d] + red[128 + d] + red[192 + d];
        // ctx layout: [B, N, D_MODEL] with head h occupying cols [h*64, h*64+64)
        ctx[((size_t)(b * N_SEQ + n)) * D_MODEL + h * D_HEAD + d] = o;
    }
}

// ---------------------------------------------------------------------------
extern "C" void kernel_launch(void* const* d_in, const int* in_sizes, int n_in,
                              void* d_out, int out_size)
{
    const float* x     = (const float*)d_in[0];   // [B,N,D]
    const float* W_qkv = (const float*)d_in[1];   // [D,3D]
    const float* W_out = (const float*)d_in[2];   // [D,D]
    float* out = (float*)d_out;

    float* qkv_buf;
    float* ctx_buf;
    // Use device-global scratch via symbol addresses taken inside kernels —
    // simplest is to reference them directly; grab raw pointers here:
    cudaGetSymbolAddress((void**)&qkv_buf, g_qkv);
    cudaGetSymbolAddress((void**)&ctx_buf, g_ctx);

    // 1) QKV projection: [4096,1024] @ [1024,3072]
    {
        dim3 grid(QKV_COLS / BN, M_ROWS / BM);
        gemm_f32<<<grid, 256>>>(x, W_qkv, qkv_buf, M_ROWS, QKV_COLS, D_MODEL);
    }

    // 2) Attention
    const long long out_elems  = (long long)B_SZ * N_SEQ * D_MODEL;              // 4,194,304
    const long long attn_elems = (long long)B_SZ * N_HEADS * N_SEQ * N_SEQ;      // 134,217,728
    const int write_attn = ((long long)out_size >= out_elems + attn_elems) ? 1 : 0;
    float* attn_ptr = write_attn ? (out + out_elems) : nullptr;
    {
        dim3 grid(N_SEQ, N_HEADS, B_SZ);
        attn_kernel<<<grid, 256>>>(qkv_buf, attn_ptr, ctx_buf, write_attn);
    }

    // 3) Output projection: [4096,1024] @ [1024,1024]
    {
        dim3 grid(D_MODEL / BN, M_ROWS / BM);
        gemm_f32<<<grid, 256>>>(ctx_buf, W_out, out, M_ROWS, D_MODEL, D_MODEL);
    }
}

// round 2
// speedup vs baseline: 15.1240x; 15.1240x over previous
#include <cuda_runtime.h>
#include <cuda_bf16.h>
#include <math.h>

#define B_SZ    2
#define N_SEQ   2048
#define D_MODEL 1024
#define N_HEADS 16
#define D_HEAD  64
#define M_ROWS  (B_SZ * N_SEQ)        // 4096
#define QKV_COLS (3 * D_MODEL)        // 3072
#define N_TILES (N_SEQ / 64)          // 32
#define N_PAIRS (N_TILES * (N_TILES + 1) / 2)  // 528

// Scratch
__device__ float g_qkv[(size_t)M_ROWS * QKV_COLS];          // ~50 MB
__device__ float g_ctx[(size_t)M_ROWS * D_MODEL];           // ~17 MB
__device__ float g_attn[(size_t)B_SZ * N_HEADS * N_SEQ * N_SEQ]; // 512 MB fallback

// ---------------------------------------------------------------------------
// fp32 GEMM: C[M,N] = A[M,K] @ B[K,N]; 128x128 tiles, BK=8, 8x8 per thread.
// M,N multiples of 128; K multiple of 8.
// ---------------------------------------------------------------------------
__global__ __launch_bounds__(256) void gemm128(const float* __restrict__ A,
                                               const float* __restrict__ Bm,
                                               float* __restrict__ C,
                                               int M, int N, int K)
{
    __shared__ float As[8][132];   // As[k][m]
    __shared__ float Bs[8][132];   // Bs[k][n]

    const int tid = threadIdx.x;
    const int tx = tid & 15;       // 0..15
    const int ty = tid >> 4;       // 0..15
    const int row0 = blockIdx.y * 128;
    const int col0 = blockIdx.x * 128;

    const int ar = tid >> 1;          // 0..127
    const int ac = (tid & 1) * 4;     // 0 or 4
    const int br = tid >> 5;          // 0..7
    const int bc = (tid & 31) * 4;    // 0..124

    float acc[8][8] = {};

    for (int k0 = 0; k0 < K; k0 += 8) {
        float4 av = *(const float4*)&A[(size_t)(row0 + ar) * K + k0 + ac];
        As[ac + 0][ar] = av.x;
        As[ac + 1][ar] = av.y;
        As[ac + 2][ar] = av.z;
        As[ac + 3][ar] = av.w;
        float4 bv = *(const float4*)&Bm[(size_t)(k0 + br) * N + col0 + bc];
        *(float4*)&Bs[br][bc] = bv;
        __syncthreads();

        #pragma unroll
        for (int kk = 0; kk < 8; kk++) {
            float a[8], b[8];
            *(float4*)&a[0] = *(const float4*)&As[kk][ty * 8];
            *(float4*)&a[4] = *(const float4*)&As[kk][ty * 8 + 4];
            *(float4*)&b[0] = *(const float4*)&Bs[kk][tx * 8];
            *(float4*)&b[4] = *(const float4*)&Bs[kk][tx * 8 + 4];
            #pragma unroll
            for (int i = 0; i < 8; i++)
                #pragma unroll
                for (int j = 0; j < 8; j++)
                    acc[i][j] = fmaf(a[i], b[j], acc[i][j]);
        }
        __syncthreads();
    }

    #pragma unroll
    for (int i = 0; i < 8; i++) {
        float* crow = &C[(size_t)(row0 + ty * 8 + i) * N + col0 + tx * 8];
        *(float4*)&crow[0] = make_float4(acc[i][0], acc[i][1], acc[i][2], acc[i][3]);
        *(float4*)&crow[4] = make_float4(acc[i][4], acc[i][5], acc[i][6], acc[i][7]);
    }
}

// ---------------------------------------------------------------------------
// Scores: S[q][k] = (Q . K)/8 for lower-triangular 64x64 tile pairs.
// Raw logits written into attn buffer; masking/softmax handled later.
// ---------------------------------------------------------------------------
__global__ __launch_bounds__(256) void scores_kernel(const float* __restrict__ qkv,
                                                     float* __restrict__ attn)
{
    const int t = blockIdx.x;
    const int h = blockIdx.y;
    const int b = blockIdx.z;

    int i = (int)((sqrtf(8.f * t + 1.f) - 1.f) * 0.5f);
    while ((i + 1) * (i + 2) / 2 <= t) i++;
    while (i * (i + 1) / 2 > t) i--;
    const int j = t - i * (i + 1) / 2;

    __shared__ float Qt[64][68];   // Qt[d][q]
    __shared__ float Kt[64][68];   // Kt[d][k]

    const int tid = threadIdx.x;
    for (int e = tid; e < 4096; e += 256) {
        int m = e >> 6, d = e & 63;
        Qt[d][m] = qkv[((size_t)(b * N_SEQ + i * 64 + m)) * QKV_COLS + h * 64 + d];
        Kt[d][m] = qkv[((size_t)(b * N_SEQ + j * 64 + m)) * QKV_COLS + D_MODEL + h * 64 + d];
    }
    __syncthreads();

    const int tx = tid & 15, ty = tid >> 4;
    float acc[4][4] = {};
    #pragma unroll 4
    for (int d = 0; d < 64; d++) {
        float4 a = *(const float4*)&Qt[d][ty * 4];
        float4 bq = *(const float4*)&Kt[d][tx * 4];
        float av[4] = {a.x, a.y, a.z, a.w};
        float bv[4] = {bq.x, bq.y, bq.z, bq.w};
        #pragma unroll
        for (int ii = 0; ii < 4; ii++)
            #pragma unroll
            for (int jj = 0; jj < 4; jj++)
                acc[ii][jj] = fmaf(av[ii], bv[jj], acc[ii][jj]);
    }

    float* base = attn + ((size_t)(b * N_HEADS + h)) * N_SEQ * N_SEQ;
    #pragma unroll
    for (int ii = 0; ii < 4; ii++) {
        int q = i * 64 + ty * 4 + ii;
        float* row = base + (size_t)q * N_SEQ + j * 64 + tx * 4;
        row[0] = acc[ii][0] * 0.125f;
        row[1] = acc[ii][1] * 0.125f;
        row[2] = acc[ii][2] * 0.125f;
        row[3] = acc[ii][3] * 0.125f;
    }
}

// ---------------------------------------------------------------------------
// Row softmax over causal prefix; zero-fill the rest. One block per row.
// ---------------------------------------------------------------------------
__global__ __launch_bounds__(256) void normalize_kernel(float* __restrict__ attn)
{
    const int n = blockIdx.x;
    const int h = blockIdx.y;
    const int b = blockIdx.z;
    const int tid = threadIdx.x;

    float* row = attn + (((size_t)(b * N_HEADS + h) * N_SEQ + n)) * N_SEQ;

    __shared__ float red[256];

    float lmax = -INFINITY;
    for (int m = tid; m <= n; m += 256) lmax = fmaxf(lmax, row[m]);
    red[tid] = lmax;
    __syncthreads();
    #pragma unroll
    for (int s = 128; s > 0; s >>= 1) {
        if (tid < s) red[tid] = fmaxf(red[tid], red[tid + s]);
        __syncthreads();
    }
    const float mx = red[0];
    __syncthreads();

    float lsum = 0.f;
    for (int m = tid; m <= n; m += 256) {
        float e = __expf(row[m] - mx);
        row[m] = e;
        lsum += e;
    }
    red[tid] = lsum;
    __syncthreads();
    #pragma unroll
    for (int s = 128; s > 0; s >>= 1) {
        if (tid < s) red[tid] += red[tid + s];
        __syncthreads();
    }
    const float inv = 1.f / red[0];
    __syncthreads();

    for (int m = tid; m <= n; m += 256) row[m] *= inv;
    for (int m = n + 1 + tid; m < N_SEQ; m += 256) row[m] = 0.f;
}

// ---------------------------------------------------------------------------
// PV: ctx[q][d] = sum_m P[q][m] * V[m][d], skipping zero (future) tiles.
// One block per (query tile i, head, batch).
// ---------------------------------------------------------------------------
__global__ __launch_bounds__(256) void pv_kernel(const float* __restrict__ attn,
                                                 const float* __restrict__ qkv,
                                                 float* __restrict__ ctx)
{
    const int i = blockIdx.x;
    const int h = blockIdx.y;
    const int b = blockIdx.z;
    const int tid = threadIdx.x;
    const int tx = tid & 15, ty = tid >> 4;

    __shared__ float Pt[64][68];   // Pt[m][q]
    __shared__ float Vs[64][68];   // Vs[m][d]

    const float* base = attn + ((size_t)(b * N_HEADS + h)) * N_SEQ * N_SEQ;
    float acc[4][4] = {};

    for (int j = 0; j <= i; j++) {
        for (int e = tid; e < 4096; e += 256) {
            int r = e >> 6, c = e & 63;
            Pt[c][r] = base[(size_t)(i * 64 + r) * N_SEQ + j * 64 + c];
            Vs[r][c] = qkv[((size_t)(b * N_SEQ + j * 64 + r)) * QKV_COLS + 2 * D_MODEL + h * 64 + c];
        }
        __syncthreads();

        #pragma unroll 4
        for (int m = 0; m < 64; m++) {
            float4 a = *(const float4*)&Pt[m][ty * 4];
            float4 bv4 = *(const float4*)&Vs[m][tx * 4];
            float av[4] = {a.x, a.y, a.z, a.w};
            float bv[4] = {bv4.x, bv4.y, bv4.z, bv4.w};
            #pragma unroll
            for (int ii = 0; ii < 4; ii++)
                #pragma unroll
                for (int jj = 0; jj < 4; jj++)
                    acc[ii][jj] = fmaf(av[ii], bv[jj], acc[ii][jj]);
        }
        __syncthreads();
    }

    #pragma unroll
    for (int ii = 0; ii < 4; ii++) {
        float* crow = &ctx[((size_t)(b * N_SEQ + i * 64 + ty * 4 + ii)) * D_MODEL + h * 64 + tx * 4];
        crow[0] = acc[ii][0];
        crow[1] = acc[ii][1];
        crow[2] = acc[ii][2];
        crow[3] = acc[ii][3];
    }
}

// ---------------------------------------------------------------------------
extern "C" void kernel_launch(void* const* d_in, const int* in_sizes, int n_in,
                              void* d_out, int out_size)
{
    const float* x     = (const float*)d_in[0];
    const float* W_qkv = (const float*)d_in[1];
    const float* W_out = (const float*)d_in[2];
    float* out = (float*)d_out;

    float *qkv_buf, *ctx_buf, *attn_scratch;
    cudaGetSymbolAddress((void**)&qkv_buf, g_qkv);
    cudaGetSymbolAddress((void**)&ctx_buf, g_ctx);
    cudaGetSymbolAddress((void**)&attn_scratch, g_attn);

    const long long out_elems  = (long long)B_SZ * N_SEQ * D_MODEL;
    const long long attn_elems = (long long)B_SZ * N_HEADS * N_SEQ * N_SEQ;
    const int write_attn = ((long long)out_size >= out_elems + attn_elems) ? 1 : 0;
    float* attn_buf = write_attn ? (out + out_elems) : attn_scratch;

    // 1) QKV projection: [4096,1024] @ [1024,3072]
    {
        dim3 grid(QKV_COLS / 128, M_ROWS / 128);
        gemm128<<<grid, 256>>>(x, W_qkv, qkv_buf, M_ROWS, QKV_COLS, D_MODEL);
    }
    // 2a) Scores (lower-triangular tiles)
    {
        dim3 grid(N_PAIRS, N_HEADS, B_SZ);
        scores_kernel<<<grid, 256>>>(qkv_buf, attn_buf);
    }
    // 2b) Softmax rows
    {
        dim3 grid(N_SEQ, N_HEADS, B_SZ);
        normalize_kernel<<<grid, 256>>>(attn_buf);
    }
    // 2c) P @ V
    {
        dim3 grid(N_TILES, N_HEADS, B_SZ);
        pv_kernel<<<grid, 256>>>(attn_buf, qkv_buf, ctx_buf);
    }
    // 3) Output projection: [4096,1024] @ [1024,1024]
    {
        dim3 grid(D_MODEL / 128, M_ROWS / 128);
        gemm128<<<grid, 256>>>(ctx_buf, W_out, out, M_ROWS, D_MODEL, D_MODEL);
    }
}

// round 3
// speedup vs baseline: 15.4810x; 1.0236x over previous
#include <cuda_runtime.h>
#include <cuda_bf16.h>
#include <math.h>

#define B_SZ    2
#define N_SEQ   2048
#define D_MODEL 1024
#define N_HEADS 16
#define D_HEAD  64
#define M_ROWS  (B_SZ * N_SEQ)        // 4096
#define QKV_COLS (3 * D_MODEL)        // 3072
#define N_TILES (N_SEQ / 64)          // 32
#define N_PAIRS (N_TILES * (N_TILES + 1) / 2)  // 528

typedef unsigned long long u64t;

// Scratch
__device__ float g_qkv[(size_t)M_ROWS * QKV_COLS];
__device__ float g_ctx[(size_t)M_ROWS * D_MODEL];
__device__ float g_attn[(size_t)B_SZ * N_HEADS * N_SEQ * N_SEQ];

// ---- f32x2 helpers (Blackwell packed fp32 FMA; 2 FLOPs/instr) --------------
__device__ __forceinline__ void fma2(u64t& d, u64t a, u64t b) {
    asm("fma.rn.f32x2 %0, %1, %2, %3;" : "=l"(d) : "l"(a), "l"(b), "l"(d));
}
__device__ __forceinline__ u64t dup2(float x) {
    u64t r; unsigned u = __float_as_uint(x);
    asm("mov.b64 %0, {%1, %2};" : "=l"(r) : "r"(u), "r"(u));
    return r;
}
__device__ __forceinline__ void mul2(u64t& d, u64t a, u64t b) {
    asm("mul.rn.f32x2 %0, %1, %2;" : "=l"(d) : "l"(a), "l"(b));
}

// ---------------------------------------------------------------------------
// fp32 GEMM with f32x2: C[M,N] = A[M,K] @ B[K,N]; 128x128 tiles, BK=8.
// ---------------------------------------------------------------------------
__global__ __launch_bounds__(256) void gemm128(const float* __restrict__ A,
                                               const float* __restrict__ Bm,
                                               float* __restrict__ C,
                                               int M, int N, int K)
{
    __shared__ float As[8][132];
    __shared__ float Bs[8][132];

    const int tid = threadIdx.x;
    const int tx = tid & 15;
    const int ty = tid >> 4;
    const int row0 = blockIdx.y * 128;
    const int col0 = blockIdx.x * 128;

    const int ar = tid >> 1;
    const int ac = (tid & 1) * 4;
    const int br = tid >> 5;
    const int bc = (tid & 31) * 4;

    u64t acc[8][4];
    #pragma unroll
    for (int i = 0; i < 8; i++)
        #pragma unroll
        for (int j = 0; j < 4; j++) acc[i][j] = 0ull;

    for (int k0 = 0; k0 < K; k0 += 8) {
        float4 av = *(const float4*)&A[(size_t)(row0 + ar) * K + k0 + ac];
        As[ac + 0][ar] = av.x;
        As[ac + 1][ar] = av.y;
        As[ac + 2][ar] = av.z;
        As[ac + 3][ar] = av.w;
        *(float4*)&Bs[br][bc] = *(const float4*)&Bm[(size_t)(k0 + br) * N + col0 + bc];
        __syncthreads();

        #pragma unroll
        for (int kk = 0; kk < 8; kk++) {
            u64t b2[4];
            #pragma unroll
            for (int j = 0; j < 4; j++)
                b2[j] = *(const u64t*)&Bs[kk][tx * 8 + j * 2];
            float a[8];
            *(float4*)&a[0] = *(const float4*)&As[kk][ty * 8];
            *(float4*)&a[4] = *(const float4*)&As[kk][ty * 8 + 4];
            #pragma unroll
            for (int i = 0; i < 8; i++) {
                u64t ad = dup2(a[i]);
                #pragma unroll
                for (int j = 0; j < 4; j++) fma2(acc[i][j], ad, b2[j]);
            }
        }
        __syncthreads();
    }

    #pragma unroll
    for (int i = 0; i < 8; i++) {
        float* crow = &C[(size_t)(row0 + ty * 8 + i) * N + col0 + tx * 8];
        #pragma unroll
        for (int j = 0; j < 4; j++) *(u64t*)&crow[j * 2] = acc[i][j];
    }
}

// ---------------------------------------------------------------------------
// Scores: raw logits S = (Q.K)/8 for lower-triangular 64x64 tile pairs.
// ---------------------------------------------------------------------------
__global__ __launch_bounds__(256) void scores_kernel(const float* __restrict__ qkv,
                                                     float* __restrict__ attn)
{
    const int t = blockIdx.x;
    const int h = blockIdx.y;
    const int b = blockIdx.z;

    int i = (int)((sqrtf(8.f * t + 1.f) - 1.f) * 0.5f);
    while ((i + 1) * (i + 2) / 2 <= t) i++;
    while (i * (i + 1) / 2 > t) i--;
    const int j = t - i * (i + 1) / 2;

    __shared__ float Qt[64][68];   // [d][q]
    __shared__ float Kt[64][68];   // [d][k]

    const int tid = threadIdx.x;
    for (int e = tid; e < 1024; e += 256) {
        int m = e >> 2, d4 = (e & 3) * 16;   // each thread moves 16 d's for one m? no:
        (void)m; (void)d4;
        break;
    }
    // load: 64 rows x 64 d, float4 over d, transpose into [d][m]
    for (int e = tid; e < 1024; e += 256) {
        int m = e >> 4, d4 = (e & 15) * 4;
        float4 qv = *(const float4*)&qkv[((size_t)(b * N_SEQ + i * 64 + m)) * QKV_COLS + h * 64 + d4];
        Qt[d4 + 0][m] = qv.x; Qt[d4 + 1][m] = qv.y; Qt[d4 + 2][m] = qv.z; Qt[d4 + 3][m] = qv.w;
        float4 kv = *(const float4*)&qkv[((size_t)(b * N_SEQ + j * 64 + m)) * QKV_COLS + D_MODEL + h * 64 + d4];
        Kt[d4 + 0][m] = kv.x; Kt[d4 + 1][m] = kv.y; Kt[d4 + 2][m] = kv.z; Kt[d4 + 3][m] = kv.w;
    }
    __syncthreads();

    const int tx = tid & 15, ty = tid >> 4;
    u64t acc[4][2];
    #pragma unroll
    for (int ii = 0; ii < 4; ii++) { acc[ii][0] = 0ull; acc[ii][1] = 0ull; }

    #pragma unroll 4
    for (int d = 0; d < 64; d++) {
        u64t b0 = *(const u64t*)&Kt[d][tx * 4];
        u64t b1 = *(const u64t*)&Kt[d][tx * 4 + 2];
        float4 a4 = *(const float4*)&Qt[d][ty * 4];
        float av[4] = {a4.x, a4.y, a4.z, a4.w};
        #pragma unroll
        for (int ii = 0; ii < 4; ii++) {
            u64t ad = dup2(av[ii]);
            fma2(acc[ii][0], ad, b0);
            fma2(acc[ii][1], ad, b1);
        }
    }

    const u64t s2 = dup2(0.125f);
    float* base = attn + ((size_t)(b * N_HEADS + h)) * N_SEQ * N_SEQ;
    #pragma unroll
    for (int ii = 0; ii < 4; ii++) {
        int q = i * 64 + ty * 4 + ii;
        float* row = base + (size_t)q * N_SEQ + j * 64 + tx * 4;
        u64t r0, r1;
        mul2(r0, acc[ii][0], s2);
        mul2(r1, acc[ii][1], s2);
        *(u64t*)&row[0] = r0;
        *(u64t*)&row[2] = r1;
    }
}

// ---------------------------------------------------------------------------
// Row softmax over causal prefix (vectorized); store-once epilogue.
// ---------------------------------------------------------------------------
__global__ __launch_bounds__(256) void normalize_kernel(float* __restrict__ attn)
{
    const int n = blockIdx.x;
    const int h = blockIdx.y;
    const int b = blockIdx.z;
    const int tid = threadIdx.x;

    float* row = attn + (((size_t)(b * N_HEADS + h) * N_SEQ + n)) * N_SEQ;
    __shared__ float red[256];

    const int P = n + 1;
    const int n4full = P >> 2;
    const int tail = P & 3;

    float lmax = -INFINITY;
    for (int m4 = tid; m4 < n4full; m4 += 256) {
        float4 v = *(const float4*)&row[m4 * 4];
        lmax = fmaxf(lmax, fmaxf(fmaxf(v.x, v.y), fmaxf(v.z, v.w)));
    }
    if (tid < tail) lmax = fmaxf(lmax, row[n4full * 4 + tid]);
    red[tid] = lmax;
    __syncthreads();
    #pragma unroll
    for (int s = 128; s > 0; s >>= 1) {
        if (tid < s) red[tid] = fmaxf(red[tid], red[tid + s]);
        __syncthreads();
    }
    const float mx = red[0];
    __syncthreads();

    float lsum = 0.f;
    for (int m4 = tid; m4 < n4full; m4 += 256) {
        float4 v = *(const float4*)&row[m4 * 4];
        lsum += __expf(v.x - mx) + __expf(v.y - mx) + __expf(v.z - mx) + __expf(v.w - mx);
    }
    if (tid < tail) lsum += __expf(row[n4full * 4 + tid] - mx);
    red[tid] = lsum;
    __syncthreads();
    #pragma unroll
    for (int s = 128; s > 0; s >>= 1) {
        if (tid < s) red[tid] += red[tid + s];
        __syncthreads();
    }
    const float inv = 1.f / red[0];
    __syncthreads();

    // final: exp*inv for prefix, zeros after — single write pass
    for (int m4 = tid; m4 < N_SEQ / 4; m4 += 256) {
        float4 o;
        if (m4 < n4full) {
            float4 v = *(const float4*)&row[m4 * 4];
            o.x = __expf(v.x - mx) * inv;
            o.y = __expf(v.y - mx) * inv;
            o.z = __expf(v.z - mx) * inv;
            o.w = __expf(v.w - mx) * inv;
        } else if (m4 == n4full && tail) {
            float4 v = *(const float4*)&row[m4 * 4];
            float vv[4] = {v.x, v.y, v.z, v.w};
            float oo[4];
            #pragma unroll
            for (int k = 0; k < 4; k++)
                oo[k] = (m4 * 4 + k < P) ? __expf(vv[k] - mx) * inv : 0.f;
            o = make_float4(oo[0], oo[1], oo[2], oo[3]);
        } else {
            o = make_float4(0.f, 0.f, 0.f, 0.f);
        }
        *(float4*)&row[m4 * 4] = o;
    }
}

// ---------------------------------------------------------------------------
// PV: ctx = P @ V over causal tiles. 128 queries x 64 dims per block.
// smem exactly 48KB: Ps[128][64] + Vs[64][64].
// ---------------------------------------------------------------------------
__global__ __launch_bounds__(256) void pv_kernel(const float* __restrict__ attn,
                                                 const float* __restrict__ qkv,
                                                 float* __restrict__ ctx)
{
    const int i = blockIdx.x;   // 128-query tile, 0..15
    const int h = blockIdx.y;
    const int b = blockIdx.z;
    const int tid = threadIdx.x;
    const int tx = tid & 15, ty = tid >> 4;

    __shared__ float Ps[128][64];   // [q][m]
    __shared__ float Vs[64][64];    // [m][d]

    const float* base = attn + ((size_t)(b * N_HEADS + h)) * N_SEQ * N_SEQ;

    u64t acc[8][2];
    #pragma unroll
    for (int ii = 0; ii < 8; ii++) { acc[ii][0] = 0ull; acc[ii][1] = 0ull; }

    const int jmax = 2 * i + 1;   // m-tiles of 64 covering causal prefix
    for (int j = 0; j <= jmax; j++) {
        // load P tile: 128 q x 64 m (float4 along m)
        for (int e = tid; e < 2048; e += 256) {
            int q = e >> 4, m4 = (e & 15) * 4;
            *(float4*)&Ps[q][m4] =
                *(const float4*)&base[(size_t)(i * 128 + q) * N_SEQ + j * 64 + m4];
        }
        // load V tile: 64 m x 64 d
        for (int e = tid; e < 1024; e += 256) {
            int m = e >> 4, d4 = (e & 15) * 4;
            *(float4*)&Vs[m][d4] =
                *(const float4*)&qkv[((size_t)(b * N_SEQ + j * 64 + m)) * QKV_COLS + 2 * D_MODEL + h * 64 + d4];
        }
        __syncthreads();

        #pragma unroll 4
        for (int m = 0; m < 64; m++) {
            u64t b0 = *(const u64t*)&Vs[m][tx * 4];
            u64t b1 = *(const u64t*)&Vs[m][tx * 4 + 2];
            #pragma unroll
            for (int ii = 0; ii < 8; ii++) {
                u64t ad = dup2(Ps[ty * 8 + ii][m]);
                fma2(acc[ii][0], ad, b0);
                fma2(acc[ii][1], ad, b1);
            }
        }
        __syncthreads();
    }

    #pragma unroll
    for (int ii = 0; ii < 8; ii++) {
        float* crow = &ctx[((size_t)(b * N_SEQ + i * 128 + ty * 8 + ii)) * D_MODEL + h * 64 + tx * 4];
        *(u64t*)&crow[0] = acc[ii][0];
        *(u64t*)&crow[2] = acc[ii][1];
    }
}

// ---------------------------------------------------------------------------
extern "C" void kernel_launch(void* const* d_in, const int* in_sizes, int n_in,
                              void* d_out, int out_size)
{
    const float* x     = (const float*)d_in[0];
    const float* W_qkv = (const float*)d_in[1];
    const float* W_out = (const float*)d_in[2];
    float* out = (float*)d_out;

    float *qkv_buf, *ctx_buf, *attn_scratch;
    cudaGetSymbolAddress((void**)&qkv_buf, g_qkv);
    cudaGetSymbolAddress((void**)&ctx_buf, g_ctx);
    cudaGetSymbolAddress((void**)&attn_scratch, g_attn);

    const long long out_elems  = (long long)B_SZ * N_SEQ * D_MODEL;
    const long long attn_elems = (long long)B_SZ * N_HEADS * N_SEQ * N_SEQ;
    const int write_attn = ((long long)out_size >= out_elems + attn_elems) ? 1 : 0;
    float* attn_buf = write_attn ? (out + out_elems) : attn_scratch;

    {   // 1) QKV projection
        dim3 grid(QKV_COLS / 128, M_ROWS / 128);
        gemm128<<<grid, 256>>>(x, W_qkv, qkv_buf, M_ROWS, QKV_COLS, D_MODEL);
    }
    {   // 2a) scores
        dim3 grid(N_PAIRS, N_HEADS, B_SZ);
        scores_kernel<<<grid, 256>>>(qkv_buf, attn_buf);
    }
    {   // 2b) softmax
        dim3 grid(N_SEQ, N_HEADS, B_SZ);
        normalize_kernel<<<grid, 256>>>(attn_buf);
    }
    {   // 2c) P @ V
        dim3 grid(N_SEQ / 128, N_HEADS, B_SZ);
        pv_kernel<<<grid, 256>>>(attn_buf, qkv_buf, ctx_buf);
    }
    {   // 3) output projection
        dim3 grid(D_MODEL / 128, M_ROWS / 128);
        gemm128<<<grid, 256>>>(ctx_buf, W_out, out, M_ROWS, D_MODEL, D_MODEL);
    }
}

// round 5
// speedup vs baseline: 29.4963x; 1.9053x over previous
#include <cuda_runtime.h>
#include <cuda_bf16.h>
#include <math.h>
#include <stdint.h>

#define B_SZ    2
#define N_SEQ   2048
#define D_MODEL 1024
#define N_HEADS 16
#define D_HEAD  64
#define M_ROWS  (B_SZ * N_SEQ)        // 4096
#define QKV_COLS (3 * D_MODEL)        // 3072
#define NT128   (N_SEQ / 128)         // 16
#define NPAIR128 (NT128 * (NT128 + 1) / 2)  // 136

// ---------------- scratch ---------------------------------------------------
__device__ float g_attn[(size_t)B_SZ * N_HEADS * N_SEQ * N_SEQ];      // fallback
__device__ __nv_bfloat16 g_xh[(size_t)M_ROWS * D_MODEL];
__device__ __nv_bfloat16 g_xl[(size_t)M_ROWS * D_MODEL];
__device__ __nv_bfloat16 g_qkvh[(size_t)M_ROWS * QKV_COLS];
__device__ __nv_bfloat16 g_qkvl[(size_t)M_ROWS * QKV_COLS];
__device__ __nv_bfloat16 g_ch[(size_t)M_ROWS * D_MODEL];
__device__ __nv_bfloat16 g_cl[(size_t)M_ROWS * D_MODEL];
__device__ __nv_bfloat16 g_wqh[(size_t)QKV_COLS * D_MODEL];   // [N][K]
__device__ __nv_bfloat16 g_wql[(size_t)QKV_COLS * D_MODEL];
__device__ __nv_bfloat16 g_woh[(size_t)D_MODEL * D_MODEL];
__device__ __nv_bfloat16 g_wol[(size_t)D_MODEL * D_MODEL];

// ---------------- warp-mma helpers ------------------------------------------
__device__ __forceinline__ uint32_t smem_u32(const void* p) {
    uint32_t a;
    asm("{ .reg .u64 t; cvta.to.shared.u64 t, %1; cvt.u32.u64 %0, t; }" : "=r"(a) : "l"(p));
    return a;
}
__device__ __forceinline__ void ldsm4(uint32_t* r, uint32_t a) {
    asm volatile("ldmatrix.sync.aligned.m8n8.x4.shared.b16 {%0,%1,%2,%3}, [%4];"
                 : "=r"(r[0]), "=r"(r[1]), "=r"(r[2]), "=r"(r[3]) : "r"(a));
}
__device__ __forceinline__ void ldsm4t(uint32_t* r, uint32_t a) {
    asm volatile("ldmatrix.sync.aligned.m8n8.x4.trans.shared.b16 {%0,%1,%2,%3}, [%4];"
                 : "=r"(r[0]), "=r"(r[1]), "=r"(r[2]), "=r"(r[3]) : "r"(a));
}
__device__ __forceinline__ void mma16816(float* c, const uint32_t* a, uint32_t b0, uint32_t b1) {
    asm volatile("mma.sync.aligned.m16n8k16.row.col.f32.bf16.bf16.f32 "
                 "{%0,%1,%2,%3}, {%4,%5,%6,%7}, {%8,%9}, {%0,%1,%2,%3};"
                 : "+f"(c[0]), "+f"(c[1]), "+f"(c[2]), "+f"(c[3])
                 : "r"(a[0]), "r"(a[1]), "r"(a[2]), "r"(a[3]), "r"(b0), "r"(b1));
}
__device__ __forceinline__ void bsplit(float v, __nv_bfloat16& h, __nv_bfloat16& l) {
    h = __float2bfloat16(v);
    l = __float2bfloat16(v - __bfloat162float(h));
}

// ---------------------------------------------------------------------------
// prep: fp32 -> hi/lo bf16 split; weight transpose+split
// ---------------------------------------------------------------------------
__global__ __launch_bounds__(256) void split_kernel(const float* __restrict__ s,
                                                    __nv_bfloat16* __restrict__ hi,
                                                    __nv_bfloat16* __restrict__ lo)
{
    size_t i = (size_t)blockIdx.x * 1024 + threadIdx.x * 4;
    float4 v = *(const float4*)&s[i];
    float vv[4] = {v.x, v.y, v.z, v.w};
    __nv_bfloat16 h[4], l[4];
    #pragma unroll
    for (int k = 0; k < 4; k++) bsplit(vv[k], h[k], l[k]);
    *(uint2*)&hi[i] = *(uint2*)h;
    *(uint2*)&lo[i] = *(uint2*)l;
}

// W[K][N] -> hi/lo[N][K]
__global__ void wtrans_split(const float* __restrict__ W,
                             __nv_bfloat16* __restrict__ hi,
                             __nv_bfloat16* __restrict__ lo, int K, int N)
{
    __shared__ float t[32][33];
    const int n0 = blockIdx.x * 32, k0 = blockIdx.y * 32;
    const int tx = threadIdx.x, ty = threadIdx.y;  // (32,8)
    for (int i = ty; i < 32; i += 8)
        t[i][tx] = W[(size_t)(k0 + i) * N + n0 + tx];
    __syncthreads();
    for (int i = ty; i < 32; i += 8) {
        float v = t[tx][i];
        __nv_bfloat16 h, l;
        bsplit(v, h, l);
        hi[(size_t)(n0 + i) * K + k0 + tx] = h;
        lo[(size_t)(n0 + i) * K + k0 + tx] = l;
    }
}

// ---------------------------------------------------------------------------
// GEMM via mma.sync: C[M,N] = A[M,K] @ Bt[N,K]^T ; operands pre-split hi/lo.
// CTA tile 128x128, BK=64, 8 warps (2m x 4n), warp tile 64x32.
// SPLIT_OUT: write C as hi/lo bf16; else fp32.
// ---------------------------------------------------------------------------
#define LDT 72    // padded smem stride (b16) for 64-wide tiles
#define SMEM_G (4 * 128 * LDT * 2)   // 73728 B

template<bool SPLIT_OUT>
__global__ __launch_bounds__(256) void gemm_mma(const __nv_bfloat16* __restrict__ ahi,
                                                const __nv_bfloat16* __restrict__ alo,
                                                const __nv_bfloat16* __restrict__ bhi,
                                                const __nv_bfloat16* __restrict__ blo,
                                                float* __restrict__ Cf,
                                                __nv_bfloat16* __restrict__ Chi,
                                                __nv_bfloat16* __restrict__ Clo,
                                                int N, int K)
{
    extern __shared__ __nv_bfloat16 sm[];
    __nv_bfloat16* Ah = sm;
    __nv_bfloat16* Al = Ah + 128 * LDT;
    __nv_bfloat16* Bh = Al + 128 * LDT;
    __nv_bfloat16* Bl = Bh + 128 * LDT;

    const int tid = threadIdx.x, lane = tid & 31, wid = tid >> 5;
    const int wm = (wid >> 2) * 64, wn = (wid & 3) * 32;
    const int row0 = blockIdx.y * 128, col0 = blockIdx.x * 128;
    const int lrow = lane & 15;            // ldmatrix row pattern
    const int lcol = (lane >> 4) * 8;      // ldmatrix col-half pattern

    const uint32_t sAh = smem_u32(Ah), sAl = smem_u32(Al);
    const uint32_t sBh = smem_u32(Bh), sBl = smem_u32(Bl);

    float c[4][4][4] = {};

    for (int k0 = 0; k0 < K; k0 += 64) {
        for (int e = tid; e < 1024; e += 256) {
            int r = e >> 3, cb = (e & 7) * 8;
            size_t ga = (size_t)(row0 + r) * K + k0 + cb;
            size_t gb = (size_t)(col0 + r) * K + k0 + cb;
            *(uint4*)(Ah + r * LDT + cb) = *(const uint4*)(ahi + ga);
            *(uint4*)(Al + r * LDT + cb) = *(const uint4*)(alo + ga);
            *(uint4*)(Bh + r * LDT + cb) = *(const uint4*)(bhi + gb);
            *(uint4*)(Bl + r * LDT + cb) = *(const uint4*)(blo + gb);
        }
        __syncthreads();

        #pragma unroll
        for (int kt = 0; kt < 4; kt++) {
            uint32_t ah[4][4], al[4][4], bh[2][4], bl[2][4];
            #pragma unroll
            for (int mt = 0; mt < 4; mt++) {
                uint32_t off = ((wm + mt * 16 + lrow) * LDT + kt * 16 + lcol) * 2;
                ldsm4(ah[mt], sAh + off);
                ldsm4(al[mt], sAl + off);
            }
            #pragma unroll
            for (int bt = 0; bt < 2; bt++) {
                uint32_t off = ((wn + bt * 16 + lrow) * LDT + kt * 16 + lcol) * 2;
                ldsm4(bh[bt], sBh + off);
                ldsm4(bl[bt], sBl + off);
            }
            #pragma unroll
            for (int mt = 0; mt < 4; mt++)
                #pragma unroll
                for (int nt = 0; nt < 4; nt++) {
                    const int bt = nt >> 1, s = nt & 1;
                    mma16816(c[mt][nt], ah[mt], bh[bt][s], bh[bt][s + 2]);
                    mma16816(c[mt][nt], al[mt], bh[bt][s], bh[bt][s + 2]);
                    mma16816(c[mt][nt], ah[mt], bl[bt][s], bl[bt][s + 2]);
                }
        }
        __syncthreads();
    }

    const int g = lane >> 2, tg = lane & 3;
    #pragma unroll
    for (int mt = 0; mt < 4; mt++)
        #pragma unroll
        for (int nt = 0; nt < 4; nt++) {
            const int row = row0 + wm + mt * 16 + g;
            const int col = col0 + wn + nt * 8 + tg * 2;
            if (SPLIT_OUT) {
                __nv_bfloat16 h0, l0, h1, l1;
                bsplit(c[mt][nt][0], h0, l0);
                bsplit(c[mt][nt][1], h1, l1);
                __nv_bfloat162 hh; hh.x = h0; hh.y = h1;
                __nv_bfloat162 ll; ll.x = l0; ll.y = l1;
                *(__nv_bfloat162*)(Chi + (size_t)row * N + col) = hh;
                *(__nv_bfloat162*)(Clo + (size_t)row * N + col) = ll;
                bsplit(c[mt][nt][2], h0, l0);
                bsplit(c[mt][nt][3], h1, l1);
                hh.x = h0; hh.y = h1; ll.x = l0; ll.y = l1;
                *(__nv_bfloat162*)(Chi + (size_t)(row + 8) * N + col) = hh;
                *(__nv_bfloat162*)(Clo + (size_t)(row + 8) * N + col) = ll;
            } else {
                *(float2*)(Cf + (size_t)row * N + col) = make_float2(c[mt][nt][0], c[mt][nt][1]);
                *(float2*)(Cf + (size_t)(row + 8) * N + col) = make_float2(c[mt][nt][2], c[mt][nt][3]);
            }
        }
}

// ---------------------------------------------------------------------------
// Scores: S = (Q.K^T)/8 for lower-triangular 128x128 tile pairs. K-dim = 64.
// ---------------------------------------------------------------------------
__global__ __launch_bounds__(256) void scores_mma(const __nv_bfloat16* __restrict__ qh,
                                                  const __nv_bfloat16* __restrict__ ql,
                                                  float* __restrict__ attn)
{
    const int t = blockIdx.x, h = blockIdx.y, b = blockIdx.z;
    int i = 0;
    while ((i + 1) * (i + 2) / 2 <= t) i++;
    const int j = t - i * (i + 1) / 2;

    extern __shared__ __nv_bfloat16 sm[];
    __nv_bfloat16* Qh = sm;
    __nv_bfloat16* Ql = Qh + 128 * LDT;
    __nv_bfloat16* Kh = Ql + 128 * LDT;
    __nv_bfloat16* Kl = Kh + 128 * LDT;

    const int tid = threadIdx.x, lane = tid & 31, wid = tid >> 5;
    const int wm = (wid >> 2) * 64, wn = (wid & 3) * 32;
    const int lrow = lane & 15, lcol = (lane >> 4) * 8;

    for (int e = tid; e < 1024; e += 256) {
        int r = e >> 3, cb = (e & 7) * 8;
        size_t qa = (size_t)(b * N_SEQ + i * 128 + r) * QKV_COLS + h * 64 + cb;
        size_t ka = (size_t)(b * N_SEQ + j * 128 + r) * QKV_COLS + D_MODEL + h * 64 + cb;
        *(uint4*)(Qh + r * LDT + cb) = *(const uint4*)(qh + qa);
        *(uint4*)(Ql + r * LDT + cb) = *(const uint4*)(ql + qa);
        *(uint4*)(Kh + r * LDT + cb) = *(const uint4*)(qh + ka);
        *(uint4*)(Kl + r * LDT + cb) = *(const uint4*)(ql + ka);
    }
    __syncthreads();

    const uint32_t sQh = smem_u32(Qh), sQl = smem_u32(Ql);
    const uint32_t sKh = smem_u32(Kh), sKl = smem_u32(Kl);

    float c[4][4][4] = {};
    #pragma unroll
    for (int kt = 0; kt < 4; kt++) {
        uint32_t ah[4][4], al[4][4], bh[2][4], bl[2][4];
        #pragma unroll
        for (int mt = 0; mt < 4; mt++) {
            uint32_t off = ((wm + mt * 16 + lrow) * LDT + kt * 16 + lcol) * 2;
            ldsm4(ah[mt], sQh + off);
            ldsm4(al[mt], sQl + off);
        }
        #pragma unroll
        for (int bt = 0; bt < 2; bt++) {
            uint32_t off = ((wn + bt * 16 + lrow) * LDT + kt * 16 + lcol) * 2;
            ldsm4(bh[bt], sKh + off);
            ldsm4(bl[bt], sKl + off);
        }
        #pragma unroll
        for (int mt = 0; mt < 4; mt++)
            #pragma unroll
            for (int nt = 0; nt < 4; nt++) {
                const int bt = nt >> 1, s = nt & 1;
                mma16816(c[mt][nt], ah[mt], bh[bt][s], bh[bt][s + 2]);
                mma16816(c[mt][nt], al[mt], bh[bt][s], bh[bt][s + 2]);
                mma16816(c[mt][nt], ah[mt], bl[bt][s], bl[bt][s + 2]);
            }
    }

    float* base = attn + ((size_t)(b * N_HEADS + h)) * N_SEQ * N_SEQ;
    const int g = lane >> 2, tg = lane & 3;
    #pragma unroll
    for (int mt = 0; mt < 4; mt++)
        #pragma unroll
        for (int nt = 0; nt < 4; nt++) {
            const int q = i * 128 + wm + mt * 16 + g;
            const int col = j * 128 + wn + nt * 8 + tg * 2;
            *(float2*)(base + (size_t)q * N_SEQ + col) =
                make_float2(c[mt][nt][0] * 0.125f, c[mt][nt][1] * 0.125f);
            *(float2*)(base + (size_t)(q + 8) * N_SEQ + col) =
                make_float2(c[mt][nt][2] * 0.125f, c[mt][nt][3] * 0.125f);
        }
}

// ---------------------------------------------------------------------------
// Row softmax over causal prefix; store-once epilogue (also zero-fills).
// ---------------------------------------------------------------------------
__global__ __launch_bounds__(256) void normalize_kernel(float* __restrict__ attn)
{
    const int n = blockIdx.x, h = blockIdx.y, b = blockIdx.z;
    const int tid = threadIdx.x;

    float* row = attn + (((size_t)(b * N_HEADS + h) * N_SEQ + n)) * N_SEQ;
    __shared__ float red[256];

    const int P = n + 1;
    const int n4full = P >> 2;
    const int tail = P & 3;

    float lmax = -INFINITY;
    for (int m4 = tid; m4 < n4full; m4 += 256) {
        float4 v = *(const float4*)&row[m4 * 4];
        lmax = fmaxf(lmax, fmaxf(fmaxf(v.x, v.y), fmaxf(v.z, v.w)));
    }
    if (tid < tail) lmax = fmaxf(lmax, row[n4full * 4 + tid]);
    red[tid] = lmax;
    __syncthreads();
    #pragma unroll
    for (int s = 128; s > 0; s >>= 1) {
        if (tid < s) red[tid] = fmaxf(red[tid], red[tid + s]);
        __syncthreads();
    }
    const float mx = red[0];
    __syncthreads();

    float lsum = 0.f;
    for (int m4 = tid; m4 < n4full; m4 += 256) {
        float4 v = *(const float4*)&row[m4 * 4];
        lsum += __expf(v.x - mx) + __expf(v.y - mx) + __expf(v.z - mx) + __expf(v.w - mx);
    }
    if (tid < tail) lsum += __expf(row[n4full * 4 + tid] - mx);
    red[tid] = lsum;
    __syncthreads();
    #pragma unroll
    for (int s = 128; s > 0; s >>= 1) {
        if (tid < s) red[tid] += red[tid + s];
        __syncthreads();
    }
    const float inv = 1.f / red[0];
    __syncthreads();

    for (int m4 = tid; m4 < N_SEQ / 4; m4 += 256) {
        float4 o;
        if (m4 < n4full) {
            float4 v = *(const float4*)&row[m4 * 4];
            o.x = __expf(v.x - mx) * inv;
            o.y = __expf(v.y - mx) * inv;
            o.z = __expf(v.z - mx) * inv;
            o.w = __expf(v.w - mx) * inv;
        } else if (m4 == n4full && tail) {
            float4 v = *(const float4*)&row[m4 * 4];
            float vv[4] = {v.x, v.y, v.z, v.w};
            float oo[4];
            #pragma unroll
            for (int k = 0; k < 4; k++)
                oo[k] = (m4 * 4 + k < P) ? __expf(vv[k] - mx) * inv : 0.f;
            o = make_float4(oo[0], oo[1], oo[2], oo[3]);
        } else {
            o = make_float4(0.f, 0.f, 0.f, 0.f);
        }
        *(float4*)&row[m4 * 4] = o;
    }
}

// ---------------------------------------------------------------------------
// PV: ctx = P @ V over causal 128-key tiles, mma.sync, split P in smem.
// CTA: 128 q x 64 d. Epilogue writes ctx hi/lo bf16 (for the out projection).
// ---------------------------------------------------------------------------
#define LDP 136
#define SMEM_PV ((2 * 128 * LDP + 2 * 128 * LDT) * 2)   // 106496 B

__global__ __launch_bounds__(256) void pv_mma(const float* __restrict__ attn,
                                              const __nv_bfloat16* __restrict__ qh,
                                              const __nv_bfloat16* __restrict__ ql,
                                              __nv_bfloat16* __restrict__ ch,
                                              __nv_bfloat16* __restrict__ cl)
{
    const int i = blockIdx.x, h = blockIdx.y, b = blockIdx.z;

    extern __shared__ __nv_bfloat16 sm[];
    __nv_bfloat16* Ph = sm;
    __nv_bfloat16* Pl = Ph + 128 * LDP;
    __nv_bfloat16* Vh = Pl + 128 * LDP;
    __nv_bfloat16* Vl = Vh + 128 * LDT;

    const int tid = threadIdx.x, lane = tid & 31, wid = tid >> 5;
    const int wm = (wid >> 1) * 32, wn = (wid & 1) * 32;
    const int lrow = lane & 15, lcol = (lane >> 4) * 8;

    const uint32_t sPh = smem_u32(Ph), sPl = smem_u32(Pl);
    const uint32_t sVh = smem_u32(Vh), sVl = smem_u32(Vl);

    const float* base = attn + ((size_t)(b * N_HEADS + h)) * N_SEQ * N_SEQ
                             + (size_t)i * 128 * N_SEQ;
    float c[2][4][4] = {};

    for (int j = 0; j <= i; j++) {
        if (j) __syncthreads();
        // P tile 128x128 fp32 -> split hi/lo bf16 in smem
        for (int e = tid; e < 4096; e += 256) {
            int r = e >> 5, c4 = (e & 31) * 4;
            float4 v = *(const float4*)(base + (size_t)r * N_SEQ + j * 128 + c4);
            float vv[4] = {v.x, v.y, v.z, v.w};
            __nv_bfloat16 hh[4], ll[4];
            #pragma unroll
            for (int k = 0; k < 4; k++) bsplit(vv[k], hh[k], ll[k]);
            *(uint2*)(Ph + r * LDP + c4) = *(uint2*)hh;
            *(uint2*)(Pl + r * LDP + c4) = *(uint2*)ll;
        }
        // V tile 128 keys x 64 d (hi/lo)
        for (int e = tid; e < 1024; e += 256) {
            int r = e >> 3, cb = (e & 7) * 8;
            size_t va = (size_t)(b * N_SEQ + j * 128 + r) * QKV_COLS + 2 * D_MODEL + h * 64 + cb;
            *(uint4*)(Vh + r * LDT + cb) = *(const uint4*)(qh + va);
            *(uint4*)(Vl + r * LDT + cb) = *(const uint4*)(ql + va);
        }
        __syncthreads();

        #pragma unroll
        for (int kt = 0; kt < 8; kt++) {
            uint32_t ah[2][4], al[2][4], vh[2][4], vl[2][4];
            #pragma unroll
            for (int mt = 0; mt < 2; mt++) {
                uint32_t off = ((wm + mt * 16 + lrow) * LDP + kt * 16 + lcol) * 2;
                ldsm4(ah[mt], sPh + off);
                ldsm4(al[mt], sPl + off);
            }
            #pragma unroll
            for (int bt = 0; bt < 2; bt++) {
                uint32_t off = ((kt * 16 + lrow) * LDT + wn + bt * 16 + lcol) * 2;
                ldsm4t(vh[bt], sVh + off);
                ldsm4t(vl[bt], sVl + off);
            }
            #pragma unroll
            for (int mt = 0; mt < 2; mt++)
                #pragma unroll
                for (int nt = 0; nt < 4; nt++) {
                    const int bt = nt >> 1, s = (nt & 1) * 2;
                    mma16816(c[mt][nt], ah[mt], vh[bt][s], vh[bt][s + 1]);
                    mma16816(c[mt][nt], al[mt], vh[bt][s], vh[bt][s + 1]);
                    mma16816(c[mt][nt], ah[mt], vl[bt][s], vl[bt][s + 1]);
                }
        }
    }

    const int g = lane >> 2, tg = lane & 3;
    #pragma unroll
    for (int mt = 0; mt < 2; mt++)
        #pragma unroll
        for (int nt = 0; nt < 4; nt++) {
            const int q = i * 128 + wm + mt * 16 + g;
            const int d = wn + nt * 8 + tg * 2;
            __nv_bfloat16 h0, l0, h1, l1;
            bsplit(c[mt][nt][0], h0, l0);
            bsplit(c[mt][nt][1], h1, l1);
            __nv_bfloat162 hh; hh.x = h0; hh.y = h1;
            __nv_bfloat162 ll; ll.x = l0; ll.y = l1;
            *(__nv_bfloat162*)(ch + (size_t)(b * N_SEQ + q) * D_MODEL + h * 64 + d) = hh;
            *(__nv_bfloat162*)(cl + (size_t)(b * N_SEQ + q) * D_MODEL + h * 64 + d) = ll;
            bsplit(c[mt][nt][2], h0, l0);
            bsplit(c[mt][nt][3], h1, l1);
            hh.x = h0; hh.y = h1; ll.x = l0; ll.y = l1;
            *(__nv_bfloat162*)(ch + (size_t)(b * N_SEQ + q + 8) * D_MODEL + h * 64 + d) = hh;
            *(__nv_bfloat162*)(cl + (size_t)(b * N_SEQ + q + 8) * D_MODEL + h * 64 + d) = ll;
        }
}

// ---------------------------------------------------------------------------
extern "C" void kernel_launch(void* const* d_in, const int* in_sizes, int n_in,
                              void* d_out, int out_size)
{
    const float* x     = (const float*)d_in[0];
    const float* W_qkv = (const float*)d_in[1];
    const float* W_out = (const float*)d_in[2];
    float* out = (float*)d_out;

    float* attn_scratch;
    __nv_bfloat16 *xh, *xl, *qkvh, *qkvl, *ch, *cl, *wqh, *wql, *woh, *wol;
    cudaGetSymbolAddress((void**)&attn_scratch, g_attn);
    cudaGetSymbolAddress((void**)&xh, g_xh);
    cudaGetSymbolAddress((void**)&xl, g_xl);
    cudaGetSymbolAddress((void**)&qkvh, g_qkvh);
    cudaGetSymbolAddress((void**)&qkvl, g_qkvl);
    cudaGetSymbolAddress((void**)&ch, g_ch);
    cudaGetSymbolAddress((void**)&cl, g_cl);
    cudaGetSymbolAddress((void**)&wqh, g_wqh);
    cudaGetSymbolAddress((void**)&wql, g_wql);
    cudaGetSymbolAddress((void**)&woh, g_woh);
    cudaGetSymbolAddress((void**)&wol, g_wol);

    cudaFuncSetAttribute(gemm_mma<true>,  cudaFuncAttributeMaxDynamicSharedMemorySize, SMEM_G);
    cudaFuncSetAttribute(gemm_mma<false>, cudaFuncAttributeMaxDynamicSharedMemorySize, SMEM_G);
    cudaFuncSetAttribute(scores_mma,      cudaFuncAttributeMaxDynamicSharedMemorySize, SMEM_G);
    cudaFuncSetAttribute(pv_mma,          cudaFuncAttributeMaxDynamicSharedMemorySize, SMEM_PV);

    const long long out_elems  = (long long)B_SZ * N_SEQ * D_MODEL;
    const long long attn_elems = (long long)B_SZ * N_HEADS * N_SEQ * N_SEQ;
    const int write_attn = ((long long)out_size >= out_elems + attn_elems) ? 1 : 0;
    float* attn_buf = write_attn ? (out + out_elems) : attn_scratch;

    // 0) prep
    split_kernel<<<(M_ROWS * D_MODEL) / 1024, 256>>>(x, xh, xl);
    {
        dim3 grid(QKV_COLS / 32, D_MODEL / 32);
        wtrans_split<<<grid, dim3(32, 8)>>>(W_qkv, wqh, wql, D_MODEL, QKV_COLS);
    }
    {
        dim3 grid(D_MODEL / 32, D_MODEL / 32);
        wtrans_split<<<grid, dim3(32, 8)>>>(W_out, woh, wol, D_MODEL, D_MODEL);
    }

    // 1) QKV projection -> split bf16 qkv
    {
        dim3 grid(QKV_COLS / 128, M_ROWS / 128);
        gemm_mma<true><<<grid, 256, SMEM_G>>>(xh, xl, wqh, wql,
                                              nullptr, qkvh, qkvl, QKV_COLS, D_MODEL);
    }
    // 2a) scores
    {
        dim3 grid(NPAIR128, N_HEADS, B_SZ);
        scores_mma<<<grid, 256, SMEM_G>>>(qkvh, qkvl, attn_buf);
    }
    // 2b) softmax
    {
        dim3 grid(N_SEQ, N_HEADS, B_SZ);
        normalize_kernel<<<grid, 256>>>(attn_buf);
    }
    // 2c) P @ V -> split bf16 ctx
    {
        dim3 grid(NT128, N_HEADS, B_SZ);
        pv_mma<<<grid, 256, SMEM_PV>>>(attn_buf, qkvh, qkvl, ch, cl);
    }
    // 3) output projection -> fp32 out
    {
        dim3 grid(D_MODEL / 128, M_ROWS / 128);
        gemm_mma<false><<<grid, 256, SMEM_G>>>(ch, cl, woh, wol,
                                               out, nullptr, nullptr, D_MODEL, D_MODEL);
    }
}